// round 5
// baseline (speedup 1.0000x reference)
#include <cuda_runtime.h>
#include <math.h>

#define Bb 64
#define Ll 128
#define Hh 128
#define Dd 16
#define NTOT (Bb*Ll*Ll)        // 1048576

typedef unsigned long long u64;

// ---------------- scratch ----------------
__device__ float g_Wt[Hh*Dd*Hh];            // [k][d*128+n]   1 MB
__device__ float g_Wrt[Dd*Hh];              // [d*128+n]
__device__ float g_encT[Bb*Hh*Ll];          // [b][k][j]      4 MB
__device__ float g_Q[(size_t)Bb*Dd*Hh*Ll];  // [b][d][n][j]   64 MB
__device__ float g_c[Bb*Ll*Dd];             // [b][j][d]
__device__ float g_LP[2u*NTOT];             // [dh][b][j][m]  8 MB

// ---------------- packed f32x2 helpers ----------------
__device__ __forceinline__ u64 ffma2(u64 a, u64 b, u64 c) {
    u64 d; asm("fma.rn.f32x2 %0, %1, %2, %3;" : "=l"(d) : "l"(a), "l"(b), "l"(c));
    return d;
}
__device__ __forceinline__ u64 dup2(float v) {
    u64 d; asm("mov.b64 %0, {%1, %2};" : "=l"(d) : "f"(v), "f"(v));
    return d;
}
__device__ __forceinline__ float2 unpack2(u64 v) {
    float2 r; asm("mov.b64 {%0, %1}, %2;" : "=f"(r.x), "=f"(r.y) : "l"(v));
    return r;
}

// ---------------- JAX threefry2x32, partitionable, key=(0,1) --------------
__device__ __forceinline__ unsigned int rotl32(unsigned int v, int s) {
    return (v << s) | (v >> (32 - s));
}
__device__ __forceinline__ unsigned int threefry_bits(unsigned int i) {
    const unsigned int ks0 = 0u, ks1 = 1u, ks2 = 0x1BD11BDAu ^ 0u ^ 1u;
    unsigned int x0 = 0u + ks0;
    unsigned int x1 = i + ks1;
#define TFR(r) { x0 += x1; x1 = rotl32(x1, r) ^ x0; }
    TFR(13) TFR(15) TFR(26) TFR(6)   x0 += ks1; x1 += ks2 + 1u;
    TFR(17) TFR(29) TFR(16) TFR(24)  x0 += ks2; x1 += ks0 + 2u;
    TFR(13) TFR(15) TFR(26) TFR(6)   x0 += ks0; x1 += ks1 + 3u;
    TFR(17) TFR(29) TFR(16) TFR(24)  x0 += ks1; x1 += ks2 + 4u;
    TFR(13) TFR(15) TFR(26) TFR(6)   x0 += ks2; x1 += ks0 + 5u;
#undef TFR
    return x0 ^ x1;
}

__device__ __forceinline__ float tanh_fast(float x) {
    float e = __expf(2.0f * x);
    return 1.0f - __fdividef(2.0f, e + 1.0f);
}

// ---------------- kernel T: W[k,n,d] -> Wt[k][d*128+n]; Wr -> Wrt ---------
__global__ void k_transpose(const float* __restrict__ W, const float* __restrict__ Wr) {
    int idx = blockIdx.x * blockDim.x + threadIdx.x;
    if (idx < Hh * Hh * Dd) {
        int k = idx >> 11;
        int rem = idx & 2047;
        int d = rem >> 7;
        int n = rem & 127;
        g_Wt[idx] = W[(k * Hh + n) * Dd + d];
    }
    if (idx < Dd * Hh) {
        int d = idx >> 7, n = idx & 127;
        g_Wrt[idx] = Wr[n * Dd + d];
    }
}

// ---------------- kernel ET: enc[b][j][k] -> encT[b][k][j] ----------------
__global__ void k_encT(const float* __restrict__ enc) {
    __shared__ float t[32][33];
    int b = blockIdx.z;
    int j0 = blockIdx.x * 32, k0 = blockIdx.y * 32;
    int tx = threadIdx.x, ty = threadIdx.y;   // block (32, 8)
#pragma unroll
    for (int i = 0; i < 32; i += 8)
        t[ty + i][tx] = enc[b * 16384 + (j0 + ty + i) * 128 + k0 + tx];
    __syncthreads();
#pragma unroll
    for (int i = 0; i < 32; i += 8)
        g_encT[b * 16384 + (k0 + ty + i) * 128 + j0 + tx] = t[tx][ty + i];
}

// ---------------- kernel C: c[b,j,d] = enc[b,j,:].Wl[:,d] + Bvec[d] -------
__global__ void k_linear(const float* __restrict__ enc, const float* __restrict__ Wl,
                         const float* __restrict__ Bvec) {
    int idx = blockIdx.x * blockDim.x + threadIdx.x;
    if (idx >= Bb * Ll * Dd) return;
    int d = idx & 15;
    int bj = idx >> 4;
    const float* e = enc + (size_t)bj * Hh;
    float acc = Bvec[d];
#pragma unroll 8
    for (int k = 0; k < Hh; k++) acc = fmaf(e[k], Wl[k * Dd + d], acc);
    g_c[idx] = acc;
}

// 4 rows (a scalar, dup'd) x 8 cols (4 packed pairs)
#define ROWOP4(r, aval) { u64 a_ = dup2(aval); \
    acc[r][0] = ffma2(a_, b01.x, acc[r][0]); \
    acc[r][1] = ffma2(a_, b01.y, acc[r][1]); \
    acc[r][2] = ffma2(a_, b23.x, acc[r][2]); \
    acc[r][3] = ffma2(a_, b23.y, acc[r][3]); }

// ---------------- kernel 1: Q[b][d][n][j] = (enc_b @ Wt_d)^T + Wrt --------
// grid (16 d, 2 jh, 64 b), block 256, tile 64j x 128n, per-thread 4x8
extern __shared__ char smemG[];
__global__ __launch_bounds__(256) void k_gemm1() {
    float* sA = (float*)smemG;                 // encT [k][64 j]  32 KB
    float* sB = (float*)(smemG + 32768);       // Wt_d [k][128 n] 64 KB
    int d = blockIdx.x, jh = blockIdx.y, b = blockIdx.z;
    int tid = threadIdx.x;
    int tx = tid & 15, ty = tid >> 4;          // n-blk = tx*8, j-blk = ty*4

    // stage sA: encT rows k, 64 j's of this half (straight float4 copy)
    {
        const float4* src = (const float4*)(g_encT + (size_t)b * 16384 + jh * 64);
        float4* dst = (float4*)sA;
        for (int idx = tid; idx < 128 * 16; idx += 256) {
            int k = idx >> 4, g = idx & 15;
            dst[k * 16 + g] = src[k * 32 + g];
        }
    }
    // stage sB: Wt[k][d*128 + n]
    {
        const float4* src = (const float4*)(g_Wt + d * 128);
        float4* dst = (float4*)sB;
        for (int idx = tid; idx < 128 * 32; idx += 256) {
            int k = idx >> 5, g = idx & 31;
            dst[k * 32 + g] = src[k * 512 + g];
        }
    }
    __syncthreads();

    u64 acc[4][4];
#pragma unroll
    for (int r = 0; r < 4; r++)
#pragma unroll
        for (int q = 0; q < 4; q++) acc[r][q] = 0ull;

#pragma unroll 8
    for (int k = 0; k < 128; k++) {
        float4 a = *(const float4*)&sA[k * 64 + ty * 4];
        ulonglong2 b01 = *(const ulonglong2*)&sB[k * 128 + tx * 8];
        ulonglong2 b23 = *(const ulonglong2*)&sB[k * 128 + tx * 8 + 4];
        ROWOP4(0, a.x) ROWOP4(1, a.y) ROWOP4(2, a.z) ROWOP4(3, a.w)
    }

    // epilogue: unpack, add Wrt, store transposed [n][j]
    float av[4][8];
#pragma unroll
    for (int r = 0; r < 4; r++)
#pragma unroll
        for (int q = 0; q < 4; q++) {
            float2 s = unpack2(acc[r][q]);
            av[r][2 * q] = s.x; av[r][2 * q + 1] = s.y;
        }
#pragma unroll
    for (int c = 0; c < 8; c++) {
        float wr = g_Wrt[d * 128 + tx * 8 + c];
        float4 o = make_float4(av[0][c] + wr, av[1][c] + wr, av[2][c] + wr, av[3][c] + wr);
        *(float4*)(g_Q + ((size_t)(b * 16 + d) * 128 + tx * 8 + c) * 128 + jh * 64 + ty * 4) = o;
    }
}

// ---------------- kernel 2: bilinear + tanh + partial logits --------------
// grid (2 jh, 2 dh, 64 b), block 256, tile 64j x 128m, per-thread 4x8, 8 d's
extern __shared__ char smemF[];
__global__ __launch_bounds__(256) void k_final(const float* __restrict__ U) {
    float* sE = (float*)smemF;                 // encT [n][128 m] 64 KB
    float* sQ = (float*)(smemF + 65536);       // Q_d  [n][64 j]  32 KB
    float* sC = (float*)(smemF + 65536 + 32768);   // c [64 j][16 d] 4 KB
    float* sU = sC + 1024;
    int jh = blockIdx.x, dh = blockIdx.y, b = blockIdx.z;
    int tid = threadIdx.x;
    int tx = tid & 15, ty = tid >> 4;          // m-blk = tx*8, j-blk = ty*4

    // stage sE (full encT for b), sC, sU
    {
        const float4* src = (const float4*)(g_encT + (size_t)b * 16384);
        float4* dst = (float4*)sE;
        for (int idx = tid; idx < 4096; idx += 256) dst[idx] = src[idx];
        const float4* csrc = (const float4*)(g_c + b * 2048 + jh * 1024);
        float4* cdst = (float4*)sC;
        for (int idx = tid; idx < 256; idx += 256) cdst[idx] = csrc[idx];
        if (tid < 16) sU[tid] = U[tid];
    }

    float logit[4][8];
#pragma unroll
    for (int r = 0; r < 4; r++)
#pragma unroll
        for (int q = 0; q < 8; q++) logit[r][q] = 0.0f;

    for (int dd = 0; dd < 8; dd++) {
        int d = dh * 8 + dd;
        __syncthreads();
        // stage sQ: Q[b][d][n][jh*64 + j] (straight float4 copy)
        {
            const float4* src = (const float4*)(g_Q + ((size_t)(b * 16 + d) * 128) * 128 + jh * 64);
            float4* dst = (float4*)sQ;
            for (int idx = tid; idx < 2048; idx += 256) {
                int n = idx >> 4, g = idx & 15;
                dst[n * 16 + g] = src[n * 32 + g];
            }
        }
        __syncthreads();

        u64 acc[4][4];
#pragma unroll
        for (int r = 0; r < 4; r++)
#pragma unroll
            for (int q = 0; q < 4; q++) acc[r][q] = 0ull;

#pragma unroll 8
        for (int n = 0; n < 128; n++) {
            float4 a = *(const float4*)&sQ[n * 64 + ty * 4];
            ulonglong2 b01 = *(const ulonglong2*)&sE[n * 128 + tx * 8];
            ulonglong2 b23 = *(const ulonglong2*)&sE[n * 128 + tx * 8 + 4];
            ROWOP4(0, a.x) ROWOP4(1, a.y) ROWOP4(2, a.z) ROWOP4(3, a.w)
        }

        float ud = sU[d];
#pragma unroll
        for (int r = 0; r < 4; r++) {
            float cr = sC[(ty * 4 + r) * 16 + d];
#pragma unroll
            for (int q = 0; q < 4; q++) {
                float2 s = unpack2(acc[r][q]);
                logit[r][2 * q]     = fmaf(ud, tanh_fast(s.x + cr), logit[r][2 * q]);
                logit[r][2 * q + 1] = fmaf(ud, tanh_fast(s.y + cr), logit[r][2 * q + 1]);
            }
        }
    }

    // write partial logits: g_LP[dh*NTOT + b*16384 + j*128 + m]
#pragma unroll
    for (int r = 0; r < 4; r++) {
        int j = jh * 64 + ty * 4 + r;
        size_t o = (size_t)dh * NTOT + (size_t)b * 16384 + (size_t)j * 128 + tx * 8;
        *(float4*)(g_LP + o)     = make_float4(logit[r][0], logit[r][1], logit[r][2], logit[r][3]);
        *(float4*)(g_LP + o + 4) = make_float4(logit[r][4], logit[r][5], logit[r][6], logit[r][7]);
    }
}

// ---------------- kernel E: combine + mask/sigmoid/RNG/entropy ------------
__global__ __launch_bounds__(256) void k_epi(const float* __restrict__ lb,
                                             float* __restrict__ out) {
    int gid = blockIdx.x * blockDim.x + threadIdx.x;   // < NTOT/4
    const float4* P0 = (const float4*)g_LP;
    const float4* P1 = P0 + (NTOT / 4);
    float4 a = P0[gid], c = P1[gid];
    float lbias = lb[0];
    float s4[4] = { a.x + c.x + lbias, a.y + c.y + lbias,
                    a.z + c.z + lbias, a.w + c.w + lbias };
    int flat0 = gid * 4;
    int j = (flat0 >> 7) & 127;
    int m0 = flat0 & 127;
    float vs[4], ve[4];
#pragma unroll
    for (int e = 0; e < 4; e++) {
        float s = s4[e];
        if (j == m0 + e) s -= 1e8f;
        s4[e] = s;
        float p = 1.0f / (1.0f + expf(-s));
        unsigned int bits = threefry_bits((unsigned int)(flat0 + e));
        float u = __uint_as_float((bits >> 9) | 0x3f800000u) - 1.0f;
        vs[e] = (u < p) ? 1.0f : 0.0f;
        float ax = fabsf(s);
        float lse = log1pf(expf(-ax));
        float spp = fmaxf(s, 0.0f) + lse;
        float spn = fmaxf(-s, 0.0f) + lse;
        ve[e] = p * spn + (1.0f - p) * spp;
    }
    ((float4*)out)[gid]                = make_float4(vs[0], vs[1], vs[2], vs[3]);
    ((float4*)(out + NTOT))[gid]       = make_float4(s4[0], s4[1], s4[2], s4[3]);
    ((float4*)(out + 2u * NTOT))[gid]  = make_float4(ve[0], ve[1], ve[2], ve[3]);
}

// ---------------- launch ----------------
extern "C" void kernel_launch(void* const* d_in, const int* in_sizes, int n_in,
                              void* d_out, int out_size) {
    const float* enc  = (const float*)d_in[0];
    const float* W    = (const float*)d_in[1];
    const float* Wl   = (const float*)d_in[2];
    const float* Wr   = (const float*)d_in[3];
    const float* U    = (const float*)d_in[4];
    const float* Bv   = (const float*)d_in[5];
    const float* lbias= (const float*)d_in[6];
    float* out = (float*)d_out;

    k_transpose<<<(Hh * Hh * Dd + 255) / 256, 256>>>(W, Wr);
    k_encT<<<dim3(4, 4, Bb), dim3(32, 8)>>>(enc);
    k_linear<<<(Bb * Ll * Dd + 255) / 256, 256>>>(enc, Wl, Bv);

    int smemG_bytes = 32768 + 65536;           // 96 KB
    cudaFuncSetAttribute(k_gemm1, cudaFuncAttributeMaxDynamicSharedMemorySize, smemG_bytes);
    k_gemm1<<<dim3(16, 2, Bb), 256, smemG_bytes>>>();

    int smemF_bytes = 65536 + 32768 + 4096 + 64;   // ~100 KB
    cudaFuncSetAttribute(k_final, cudaFuncAttributeMaxDynamicSharedMemorySize, smemF_bytes);
    k_final<<<dim3(2, 2, Bb), 256, smemF_bytes>>>(U);

    k_epi<<<NTOT / 4 / 256, 256>>>(lbias, out);
}

// round 6
// speedup vs baseline: 1.4538x; 1.4538x over previous
#include <cuda_runtime.h>
#include <math.h>

#define Bb 64
#define Ll 128
#define Hh 128
#define Dd 16
#define NTOT (Bb*Ll*Ll)        // 1048576

typedef unsigned long long u64;

// ---------------- scratch ----------------
__device__ float g_Wt[Hh*Dd*Hh];            // [k][d*128+n]   1 MB
__device__ float g_Wrt[Dd*Hh];              // [d*128+n]
__device__ float g_encT[Bb*Hh*Ll];          // [b][k][j]      4 MB
__device__ float g_Q[(size_t)Bb*Dd*Hh*Ll];  // [b][d][n][j]   64 MB
__device__ float g_c[Bb*Ll*Dd];             // [b][j][d]
__device__ float g_LP[2u*NTOT];             // [dh][b][j][m]  8 MB

// ---------------- packed f32x2 helpers ----------------
__device__ __forceinline__ u64 ffma2(u64 a, u64 b, u64 c) {
    u64 d; asm("fma.rn.f32x2 %0, %1, %2, %3;" : "=l"(d) : "l"(a), "l"(b), "l"(c));
    return d;
}
__device__ __forceinline__ u64 dup2(float v) {
    u64 d; asm("mov.b64 %0, {%1, %2};" : "=l"(d) : "f"(v), "f"(v));
    return d;
}
__device__ __forceinline__ float2 unpack2(u64 v) {
    float2 r; asm("mov.b64 {%0, %1}, %2;" : "=f"(r.x), "=f"(r.y) : "l"(v));
    return r;
}

// ---------------- JAX threefry2x32, partitionable, key=(0,1) --------------
__device__ __forceinline__ unsigned int rotl32(unsigned int v, int s) {
    return (v << s) | (v >> (32 - s));
}
__device__ __forceinline__ unsigned int threefry_bits(unsigned int i) {
    const unsigned int ks0 = 0u, ks1 = 1u, ks2 = 0x1BD11BDAu ^ 0u ^ 1u;
    unsigned int x0 = 0u + ks0;
    unsigned int x1 = i + ks1;
#define TFR(r) { x0 += x1; x1 = rotl32(x1, r) ^ x0; }
    TFR(13) TFR(15) TFR(26) TFR(6)   x0 += ks1; x1 += ks2 + 1u;
    TFR(17) TFR(29) TFR(16) TFR(24)  x0 += ks2; x1 += ks0 + 2u;
    TFR(13) TFR(15) TFR(26) TFR(6)   x0 += ks0; x1 += ks1 + 3u;
    TFR(17) TFR(29) TFR(16) TFR(24)  x0 += ks1; x1 += ks2 + 4u;
    TFR(13) TFR(15) TFR(26) TFR(6)   x0 += ks2; x1 += ks0 + 5u;
#undef TFR
    return x0 ^ x1;
}

__device__ __forceinline__ float tanh_fast(float x) {
    float e = __expf(2.0f * x);
    return 1.0f - __fdividef(2.0f, e + 1.0f);
}

// ---------------- kernel T: W[k,n,d] -> Wt[k][d*128+n]; Wr -> Wrt ---------
__global__ void k_transpose(const float* __restrict__ W, const float* __restrict__ Wr) {
    int idx = blockIdx.x * blockDim.x + threadIdx.x;
    if (idx < Hh * Hh * Dd) {
        int k = idx >> 11;
        int rem = idx & 2047;
        int d = rem >> 7;
        int n = rem & 127;
        g_Wt[idx] = W[(k * Hh + n) * Dd + d];
    }
    if (idx < Dd * Hh) {
        int d = idx >> 7, n = idx & 127;
        g_Wrt[idx] = Wr[n * Dd + d];
    }
}

// ---------------- kernel ET: enc[b][j][k] -> encT[b][k][j] ----------------
__global__ void k_encT(const float* __restrict__ enc) {
    __shared__ float t[32][33];
    int b = blockIdx.z;
    int j0 = blockIdx.x * 32, k0 = blockIdx.y * 32;
    int tx = threadIdx.x, ty = threadIdx.y;   // block (32, 8)
#pragma unroll
    for (int i = 0; i < 32; i += 8)
        t[ty + i][tx] = enc[b * 16384 + (j0 + ty + i) * 128 + k0 + tx];
    __syncthreads();
#pragma unroll
    for (int i = 0; i < 32; i += 8)
        g_encT[b * 16384 + (k0 + ty + i) * 128 + j0 + tx] = t[tx][ty + i];
}

// ---------------- kernel C: c[b,j,d] = enc[b,j,:].Wl[:,d] + Bvec[d] -------
__global__ void k_linear(const float* __restrict__ enc, const float* __restrict__ Wl,
                         const float* __restrict__ Bvec) {
    int idx = blockIdx.x * blockDim.x + threadIdx.x;
    if (idx >= Bb * Ll * Dd) return;
    int d = idx & 15;
    int bj = idx >> 4;
    const float* e = enc + (size_t)bj * Hh;
    float acc = Bvec[d];
#pragma unroll 8
    for (int k = 0; k < Hh; k++) acc = fmaf(e[k], Wl[k * Dd + d], acc);
    g_c[idx] = acc;
}

// 4 rows (a scalar, dup'd) x 8 cols: cols tx*4..+3 (b01) and 64+tx*4..+3 (b23)
#define ROWOP4(r, aval) { u64 a_ = dup2(aval); \
    acc[r][0] = ffma2(a_, b01.x, acc[r][0]); \
    acc[r][1] = ffma2(a_, b01.y, acc[r][1]); \
    acc[r][2] = ffma2(a_, b23.x, acc[r][2]); \
    acc[r][3] = ffma2(a_, b23.y, acc[r][3]); }

// ---------------- kernel 1: Q[b][d][n][j] = (enc_b @ Wt_d)^T + Wrt --------
// grid (16 d, 2 jh, 64 b), block 256, tile 64j x 128n, per-thread 4x(4+4)
extern __shared__ char smemG[];
__global__ __launch_bounds__(256) void k_gemm1() {
    float* sA = (float*)smemG;                 // encT [k][64 j]  32 KB
    float* sB = (float*)(smemG + 32768);       // Wt_d [k][128 n] 64 KB
    int d = blockIdx.x, jh = blockIdx.y, b = blockIdx.z;
    int tid = threadIdx.x;
    int tx = tid & 15, ty = tid >> 4;          // cols tx*4 & 64+tx*4, j-blk ty*4

    // stage sA: encT rows k, 64 j's of this half (straight float4 copy)
    {
        const float4* src = (const float4*)(g_encT + (size_t)b * 16384 + jh * 64);
        float4* dst = (float4*)sA;
        for (int idx = tid; idx < 128 * 16; idx += 256) {
            int k = idx >> 4, g = idx & 15;
            dst[k * 16 + g] = src[k * 32 + g];
        }
    }
    // stage sB: Wt[k][d*128 + n]
    {
        const float4* src = (const float4*)(g_Wt + d * 128);
        float4* dst = (float4*)sB;
        for (int idx = tid; idx < 128 * 32; idx += 256) {
            int k = idx >> 5, g = idx & 31;
            dst[k * 32 + g] = src[k * 512 + g];
        }
    }
    __syncthreads();

    u64 acc[4][4];
#pragma unroll
    for (int r = 0; r < 4; r++)
#pragma unroll
        for (int q = 0; q < 4; q++) acc[r][q] = 0ull;

#pragma unroll 8
    for (int k = 0; k < 128; k++) {
        float4 a = *(const float4*)&sA[k * 64 + ty * 4];
        ulonglong2 b01 = *(const ulonglong2*)&sB[k * 128 + tx * 4];        // 16B stride: 2 wf
        ulonglong2 b23 = *(const ulonglong2*)&sB[k * 128 + 64 + tx * 4];   // 2 wf
        ROWOP4(0, a.x) ROWOP4(1, a.y) ROWOP4(2, a.z) ROWOP4(3, a.w)
    }

    // epilogue: unpack, add Wrt, store transposed [n][j]
    float av[4][8];   // [row r][c: 0..3 -> tx*4+c, 4..7 -> 64+tx*4+(c-4)]
#pragma unroll
    for (int r = 0; r < 4; r++)
#pragma unroll
        for (int q = 0; q < 4; q++) {
            float2 s = unpack2(acc[r][q]);
            av[r][2 * q] = s.x; av[r][2 * q + 1] = s.y;
        }
#pragma unroll
    for (int c = 0; c < 8; c++) {
        int col = (c < 4) ? (tx * 4 + c) : (64 + tx * 4 + (c - 4));
        float wr = g_Wrt[d * 128 + col];
        float4 o = make_float4(av[0][c] + wr, av[1][c] + wr, av[2][c] + wr, av[3][c] + wr);
        *(float4*)(g_Q + ((size_t)(b * 16 + d) * 128 + col) * 128 + jh * 64 + ty * 4) = o;
    }
}

// ---------------- kernel 2: bilinear + tanh + partial logits --------------
// grid (2 jh, 2 dh, 64 b), block 256, tile 64j x 128m, per-thread 4x(4+4), 8 d's
extern __shared__ char smemF[];
__global__ __launch_bounds__(256) void k_final(const float* __restrict__ U) {
    float* sE = (float*)smemF;                 // encT [n][128 m] 64 KB
    float* sQ = (float*)(smemF + 65536);       // Q_d  [n][64 j]  32 KB
    float* sC = (float*)(smemF + 65536 + 32768);   // c [64 j][16 d] 4 KB
    float* sU = sC + 1024;
    int jh = blockIdx.x, dh = blockIdx.y, b = blockIdx.z;
    int tid = threadIdx.x;
    int tx = tid & 15, ty = tid >> 4;          // m cols tx*4 & 64+tx*4, j-blk ty*4

    // stage sE (full encT for b), sC, sU
    {
        const float4* src = (const float4*)(g_encT + (size_t)b * 16384);
        float4* dst = (float4*)sE;
        for (int idx = tid; idx < 4096; idx += 256) dst[idx] = src[idx];
        const float4* csrc = (const float4*)(g_c + b * 2048 + jh * 1024);
        float4* cdst = (float4*)sC;
        for (int idx = tid; idx < 256; idx += 256) cdst[idx] = csrc[idx];
        if (tid < 16) sU[tid] = U[tid];
    }

    float logit[4][8];
#pragma unroll
    for (int r = 0; r < 4; r++)
#pragma unroll
        for (int q = 0; q < 8; q++) logit[r][q] = 0.0f;

    for (int dd = 0; dd < 8; dd++) {
        int d = dh * 8 + dd;
        __syncthreads();
        // stage sQ: Q[b][d][n][jh*64 + j] (straight float4 copy)
        {
            const float4* src = (const float4*)(g_Q + ((size_t)(b * 16 + d) * 128) * 128 + jh * 64);
            float4* dst = (float4*)sQ;
            for (int idx = tid; idx < 2048; idx += 256) {
                int n = idx >> 4, g = idx & 15;
                dst[n * 16 + g] = src[n * 32 + g];
            }
        }
        __syncthreads();

        u64 acc[4][4];
#pragma unroll
        for (int r = 0; r < 4; r++)
#pragma unroll
            for (int q = 0; q < 4; q++) acc[r][q] = 0ull;

#pragma unroll 8
        for (int n = 0; n < 128; n++) {
            float4 a = *(const float4*)&sQ[n * 64 + ty * 4];
            ulonglong2 b01 = *(const ulonglong2*)&sE[n * 128 + tx * 4];
            ulonglong2 b23 = *(const ulonglong2*)&sE[n * 128 + 64 + tx * 4];
            ROWOP4(0, a.x) ROWOP4(1, a.y) ROWOP4(2, a.z) ROWOP4(3, a.w)
        }

        float ud = sU[d];
#pragma unroll
        for (int r = 0; r < 4; r++) {
            float cr = sC[(ty * 4 + r) * 16 + d];
#pragma unroll
            for (int q = 0; q < 4; q++) {
                float2 s = unpack2(acc[r][q]);
                logit[r][2 * q]     = fmaf(ud, tanh_fast(s.x + cr), logit[r][2 * q]);
                logit[r][2 * q + 1] = fmaf(ud, tanh_fast(s.y + cr), logit[r][2 * q + 1]);
            }
        }
    }

    // write partial logits: g_LP[dh*NTOT + b*16384 + j*128 + m], split cols
#pragma unroll
    for (int r = 0; r < 4; r++) {
        int j = jh * 64 + ty * 4 + r;
        size_t o = (size_t)dh * NTOT + (size_t)b * 16384 + (size_t)j * 128;
        *(float4*)(g_LP + o + tx * 4)      = make_float4(logit[r][0], logit[r][1], logit[r][2], logit[r][3]);
        *(float4*)(g_LP + o + 64 + tx * 4) = make_float4(logit[r][4], logit[r][5], logit[r][6], logit[r][7]);
    }
}

// ---------------- kernel E: combine + mask/sigmoid/RNG/entropy ------------
__global__ __launch_bounds__(256) void k_epi(const float* __restrict__ lb,
                                             float* __restrict__ out) {
    int gid = blockIdx.x * blockDim.x + threadIdx.x;   // < NTOT/4
    const float4* P0 = (const float4*)g_LP;
    const float4* P1 = P0 + (NTOT / 4);
    float4 a = P0[gid], c = P1[gid];
    float lbias = lb[0];
    float s4[4] = { a.x + c.x + lbias, a.y + c.y + lbias,
                    a.z + c.z + lbias, a.w + c.w + lbias };
    int flat0 = gid * 4;
    int j = (flat0 >> 7) & 127;
    int m0 = flat0 & 127;
    float vs[4], ve[4];
#pragma unroll
    for (int e = 0; e < 4; e++) {
        float s = s4[e];
        if (j == m0 + e) s -= 1e8f;
        s4[e] = s;
        float p = 1.0f / (1.0f + expf(-s));
        unsigned int bits = threefry_bits((unsigned int)(flat0 + e));
        float u = __uint_as_float((bits >> 9) | 0x3f800000u) - 1.0f;
        vs[e] = (u < p) ? 1.0f : 0.0f;
        float ax = fabsf(s);
        float lse = log1pf(expf(-ax));
        float spp = fmaxf(s, 0.0f) + lse;
        float spn = fmaxf(-s, 0.0f) + lse;
        ve[e] = p * spn + (1.0f - p) * spp;
    }
    ((float4*)out)[gid]                = make_float4(vs[0], vs[1], vs[2], vs[3]);
    ((float4*)(out + NTOT))[gid]       = make_float4(s4[0], s4[1], s4[2], s4[3]);
    ((float4*)(out + 2u * NTOT))[gid]  = make_float4(ve[0], ve[1], ve[2], ve[3]);
}

// ---------------- launch ----------------
extern "C" void kernel_launch(void* const* d_in, const int* in_sizes, int n_in,
                              void* d_out, int out_size) {
    const float* enc  = (const float*)d_in[0];
    const float* W    = (const float*)d_in[1];
    const float* Wl   = (const float*)d_in[2];
    const float* Wr   = (const float*)d_in[3];
    const float* U    = (const float*)d_in[4];
    const float* Bv   = (const float*)d_in[5];
    const float* lbias= (const float*)d_in[6];
    float* out = (float*)d_out;

    k_transpose<<<(Hh * Hh * Dd + 255) / 256, 256>>>(W, Wr);
    k_encT<<<dim3(4, 4, Bb), dim3(32, 8)>>>(enc);
    k_linear<<<(Bb * Ll * Dd + 255) / 256, 256>>>(enc, Wl, Bv);

    int smemG_bytes = 32768 + 65536;           // 96 KB
    cudaFuncSetAttribute(k_gemm1, cudaFuncAttributeMaxDynamicSharedMemorySize, smemG_bytes);
    k_gemm1<<<dim3(16, 2, Bb), 256, smemG_bytes>>>();

    int smemF_bytes = 65536 + 32768 + 4096 + 64;   // ~100 KB
    cudaFuncSetAttribute(k_final, cudaFuncAttributeMaxDynamicSharedMemorySize, smemF_bytes);
    k_final<<<dim3(2, 2, Bb), 256, smemF_bytes>>>(U);

    k_epi<<<NTOT / 4 / 256, 256>>>(lbias, out);
}

// round 7
// speedup vs baseline: 1.4862x; 1.0223x over previous
#include <cuda_runtime.h>
#include <math.h>

#define Bb 64
#define Ll 128
#define Hh 128
#define Dd 16
#define NTOT (Bb*Ll*Ll)        // 1048576

typedef unsigned long long u64;

// ---------------- scratch ----------------
__device__ float g_Wt[Hh*Dd*Hh];            // [k][d*128+n]   1 MB
__device__ float g_Wrt[Dd*Hh];              // [d*128+n]
__device__ float g_encT[Bb*Hh*Ll];          // [b][k][j]      4 MB
__device__ float g_Q[(size_t)Bb*Dd*Hh*Ll];  // [b][d][n][j]   64 MB
__device__ float g_c[Bb*Ll*Dd];             // [b][j][d]
__device__ float g_LP[2u*NTOT];             // [dh][b][j][m]  8 MB

// ---------------- packed f32x2 helpers ----------------
__device__ __forceinline__ u64 ffma2(u64 a, u64 b, u64 c) {
    u64 d; asm("fma.rn.f32x2 %0, %1, %2, %3;" : "=l"(d) : "l"(a), "l"(b), "l"(c));
    return d;
}
__device__ __forceinline__ u64 dup2(float v) {
    u64 d; asm("mov.b64 %0, {%1, %2};" : "=l"(d) : "f"(v), "f"(v));
    return d;
}
__device__ __forceinline__ float2 unpack2(u64 v) {
    float2 r; asm("mov.b64 {%0, %1}, %2;" : "=f"(r.x), "=f"(r.y) : "l"(v));
    return r;
}

// ---------------- JAX threefry2x32, partitionable, key=(0,1) --------------
__device__ __forceinline__ unsigned int rotl32(unsigned int v, int s) {
    return (v << s) | (v >> (32 - s));
}
__device__ __forceinline__ unsigned int threefry_bits(unsigned int i) {
    const unsigned int ks0 = 0u, ks1 = 1u, ks2 = 0x1BD11BDAu ^ 0u ^ 1u;
    unsigned int x0 = 0u + ks0;
    unsigned int x1 = i + ks1;
#define TFR(r) { x0 += x1; x1 = rotl32(x1, r) ^ x0; }
    TFR(13) TFR(15) TFR(26) TFR(6)   x0 += ks1; x1 += ks2 + 1u;
    TFR(17) TFR(29) TFR(16) TFR(24)  x0 += ks2; x1 += ks0 + 2u;
    TFR(13) TFR(15) TFR(26) TFR(6)   x0 += ks0; x1 += ks1 + 3u;
    TFR(17) TFR(29) TFR(16) TFR(24)  x0 += ks1; x1 += ks2 + 4u;
    TFR(13) TFR(15) TFR(26) TFR(6)   x0 += ks2; x1 += ks0 + 5u;
#undef TFR
    return x0 ^ x1;
}

__device__ __forceinline__ float tanh_fast(float x) {
    float e = __expf(2.0f * x);
    return 1.0f - __fdividef(2.0f, e + 1.0f);
}

// ---------------- kernel T: W[k,n,d] -> Wt[k][d*128+n]; Wr -> Wrt ---------
__global__ void k_transpose(const float* __restrict__ W, const float* __restrict__ Wr) {
    int idx = blockIdx.x * blockDim.x + threadIdx.x;
    if (idx < Hh * Hh * Dd) {
        int k = idx >> 11;
        int rem = idx & 2047;
        int d = rem >> 7;
        int n = rem & 127;
        g_Wt[idx] = W[(k * Hh + n) * Dd + d];
    }
    if (idx < Dd * Hh) {
        int d = idx >> 7, n = idx & 127;
        g_Wrt[idx] = Wr[n * Dd + d];
    }
}

// ---------------- kernel ET: enc[b][j][k] -> encT[b][k][j] ----------------
__global__ void k_encT(const float* __restrict__ enc) {
    __shared__ float t[32][33];
    int b = blockIdx.z;
    int j0 = blockIdx.x * 32, k0 = blockIdx.y * 32;
    int tx = threadIdx.x, ty = threadIdx.y;   // block (32, 8)
#pragma unroll
    for (int i = 0; i < 32; i += 8)
        t[ty + i][tx] = enc[b * 16384 + (j0 + ty + i) * 128 + k0 + tx];
    __syncthreads();
#pragma unroll
    for (int i = 0; i < 32; i += 8)
        g_encT[b * 16384 + (k0 + ty + i) * 128 + j0 + tx] = t[tx][ty + i];
}

// ---------------- kernel C: c[b,j,d] = enc[b,j,:].Wl[:,d] + Bvec[d] -------
__global__ void k_linear(const float* __restrict__ enc, const float* __restrict__ Wl,
                         const float* __restrict__ Bvec) {
    int idx = blockIdx.x * blockDim.x + threadIdx.x;
    if (idx >= Bb * Ll * Dd) return;
    int d = idx & 15;
    int bj = idx >> 4;
    const float* e = enc + (size_t)bj * Hh;
    float acc = Bvec[d];
#pragma unroll 8
    for (int k = 0; k < Hh; k++) acc = fmaf(e[k], Wl[k * Dd + d], acc);
    g_c[idx] = acc;
}

// 4 rows (a scalar, dup'd) x 8 cols: cols tx*4..+3 (b01) and 64+tx*4..+3 (b23)
#define ROWOP4(r, aval) { u64 a_ = dup2(aval); \
    acc[r][0] = ffma2(a_, b01.x, acc[r][0]); \
    acc[r][1] = ffma2(a_, b01.y, acc[r][1]); \
    acc[r][2] = ffma2(a_, b23.x, acc[r][2]); \
    acc[r][3] = ffma2(a_, b23.y, acc[r][3]); }

// ---------------- kernel 1: Q[b][d][n][j] = (enc_b @ Wt_d)^T + Wrt --------
// grid (16 d, 2 jh, 64 b), block 256, tile 64j x 128n, per-thread 4x(4+4)
// inner loop software-pipelined: prefetch k+1 operands before k's FFMA2s
extern __shared__ char smemG[];
__global__ __launch_bounds__(256) void k_gemm1() {
    float* sA = (float*)smemG;                 // encT [k][64 j]  32 KB
    float* sB = (float*)(smemG + 32768);       // Wt_d [k][128 n] 64 KB (+1KB pad)
    int d = blockIdx.x, jh = blockIdx.y, b = blockIdx.z;
    int tid = threadIdx.x;
    int tx = tid & 15, ty = tid >> 4;

    // stage sA: encT rows k, 64 j's of this half
    {
        const float4* src = (const float4*)(g_encT + (size_t)b * 16384 + jh * 64);
        float4* dst = (float4*)sA;
        for (int idx = tid; idx < 128 * 16; idx += 256) {
            int k = idx >> 4, g = idx & 15;
            dst[k * 16 + g] = src[k * 32 + g];
        }
    }
    // stage sB: Wt[k][d*128 + n]
    {
        const float4* src = (const float4*)(g_Wt + d * 128);
        float4* dst = (float4*)sB;
        for (int idx = tid; idx < 128 * 32; idx += 256) {
            int k = idx >> 5, g = idx & 31;
            dst[k * 32 + g] = src[k * 512 + g];
        }
    }
    __syncthreads();

    u64 acc[4][4];
#pragma unroll
    for (int r = 0; r < 4; r++)
#pragma unroll
        for (int q = 0; q < 4; q++) acc[r][q] = 0ull;

    float4 a_nx = *(const float4*)&sA[ty * 4];
    ulonglong2 b01_nx = *(const ulonglong2*)&sB[tx * 4];
    ulonglong2 b23_nx = *(const ulonglong2*)&sB[64 + tx * 4];
#pragma unroll 4
    for (int k = 0; k < 128; k++) {
        float4 a = a_nx;
        ulonglong2 b01 = b01_nx, b23 = b23_nx;
        int kn = k + 1;   // k=127: stray read into 1KB pad, value unused
        a_nx  = *(const float4*)&sA[kn * 64 + ty * 4];
        b01_nx = *(const ulonglong2*)&sB[kn * 128 + tx * 4];
        b23_nx = *(const ulonglong2*)&sB[kn * 128 + 64 + tx * 4];
        ROWOP4(0, a.x) ROWOP4(1, a.y) ROWOP4(2, a.z) ROWOP4(3, a.w)
    }

    // epilogue: unpack, add Wrt, store transposed [n][j]
    float av[4][8];
#pragma unroll
    for (int r = 0; r < 4; r++)
#pragma unroll
        for (int q = 0; q < 4; q++) {
            float2 s = unpack2(acc[r][q]);
            av[r][2 * q] = s.x; av[r][2 * q + 1] = s.y;
        }
#pragma unroll
    for (int c = 0; c < 8; c++) {
        int col = (c < 4) ? (tx * 4 + c) : (64 + tx * 4 + (c - 4));
        float wr = g_Wrt[d * 128 + col];
        float4 o = make_float4(av[0][c] + wr, av[1][c] + wr, av[2][c] + wr, av[3][c] + wr);
        *(float4*)(g_Q + ((size_t)(b * 16 + d) * 128 + col) * 128 + jh * 64 + ty * 4) = o;
    }
}

// ---------------- kernel 2: bilinear + tanh + partial logits --------------
// grid (2 jh, 2 dh, 64 b), block 256, tile 64j x 128m, per-thread 4x(4+4), 8 d's
extern __shared__ char smemF[];
__global__ __launch_bounds__(256) void k_final(const float* __restrict__ U) {
    float* sE = (float*)smemF;                 // encT [n][128 m] 64 KB
    float* sQ = (float*)(smemF + 65536);       // Q_d  [n][64 j]  32 KB
    float* sC = (float*)(smemF + 65536 + 32768);   // c [64 j][16 d] 4 KB
    float* sU = sC + 1024;
    int jh = blockIdx.x, dh = blockIdx.y, b = blockIdx.z;
    int tid = threadIdx.x;
    int tx = tid & 15, ty = tid >> 4;

    // stage sE (full encT for b), sC, sU
    {
        const float4* src = (const float4*)(g_encT + (size_t)b * 16384);
        float4* dst = (float4*)sE;
        for (int idx = tid; idx < 4096; idx += 256) dst[idx] = src[idx];
        const float4* csrc = (const float4*)(g_c + b * 2048 + jh * 1024);
        float4* cdst = (float4*)sC;
        for (int idx = tid; idx < 256; idx += 256) cdst[idx] = csrc[idx];
        if (tid < 16) sU[tid] = U[tid];
    }

    float logit[4][8];
#pragma unroll
    for (int r = 0; r < 4; r++)
#pragma unroll
        for (int q = 0; q < 8; q++) logit[r][q] = 0.0f;

    for (int dd = 0; dd < 8; dd++) {
        int d = dh * 8 + dd;
        __syncthreads();
        // stage sQ: Q[b][d][n][jh*64 + j]
        {
            const float4* src = (const float4*)(g_Q + ((size_t)(b * 16 + d) * 128) * 128 + jh * 64);
            float4* dst = (float4*)sQ;
            for (int idx = tid; idx < 2048; idx += 256) {
                int n = idx >> 4, g = idx & 15;
                dst[n * 16 + g] = src[n * 32 + g];
            }
        }
        __syncthreads();

        u64 acc[4][4];
#pragma unroll
        for (int r = 0; r < 4; r++)
#pragma unroll
            for (int q = 0; q < 4; q++) acc[r][q] = 0ull;

        float4 a_nx = *(const float4*)&sQ[ty * 4];
        ulonglong2 b01_nx = *(const ulonglong2*)&sE[tx * 4];
        ulonglong2 b23_nx = *(const ulonglong2*)&sE[64 + tx * 4];
#pragma unroll 4
        for (int n = 0; n < 128; n++) {
            float4 a = a_nx;
            ulonglong2 b01 = b01_nx, b23 = b23_nx;
            int nn = n + 1;   // n=127: stray reads land in following allocated regions
            a_nx  = *(const float4*)&sQ[nn * 64 + ty * 4];
            b01_nx = *(const ulonglong2*)&sE[nn * 128 + tx * 4];
            b23_nx = *(const ulonglong2*)&sE[nn * 128 + 64 + tx * 4];
            ROWOP4(0, a.x) ROWOP4(1, a.y) ROWOP4(2, a.z) ROWOP4(3, a.w)
        }

        float ud = sU[d];
#pragma unroll
        for (int r = 0; r < 4; r++) {
            float cr = sC[(ty * 4 + r) * 16 + d];
#pragma unroll
            for (int q = 0; q < 4; q++) {
                float2 s = unpack2(acc[r][q]);
                logit[r][2 * q]     = fmaf(ud, tanh_fast(s.x + cr), logit[r][2 * q]);
                logit[r][2 * q + 1] = fmaf(ud, tanh_fast(s.y + cr), logit[r][2 * q + 1]);
            }
        }
    }

    // write partial logits: g_LP[dh*NTOT + b*16384 + j*128 + m], split cols
#pragma unroll
    for (int r = 0; r < 4; r++) {
        int j = jh * 64 + ty * 4 + r;
        size_t o = (size_t)dh * NTOT + (size_t)b * 16384 + (size_t)j * 128;
        *(float4*)(g_LP + o + tx * 4)      = make_float4(logit[r][0], logit[r][1], logit[r][2], logit[r][3]);
        *(float4*)(g_LP + o + 64 + tx * 4) = make_float4(logit[r][4], logit[r][5], logit[r][6], logit[r][7]);
    }
}

// ---------------- kernel E: combine + mask/sigmoid/RNG/entropy ------------
__global__ __launch_bounds__(256) void k_epi(const float* __restrict__ lb,
                                             float* __restrict__ out) {
    int gid = blockIdx.x * blockDim.x + threadIdx.x;   // < NTOT/4
    const float4* P0 = (const float4*)g_LP;
    const float4* P1 = P0 + (NTOT / 4);
    float4 a = P0[gid], c = P1[gid];
    float lbias = lb[0];
    float s4[4] = { a.x + c.x + lbias, a.y + c.y + lbias,
                    a.z + c.z + lbias, a.w + c.w + lbias };
    int flat0 = gid * 4;
    int j = (flat0 >> 7) & 127;
    int m0 = flat0 & 127;
    float vs[4], ve[4];
#pragma unroll
    for (int e = 0; e < 4; e++) {
        float s = s4[e];
        if (j == m0 + e) s -= 1e8f;
        s4[e] = s;
        float p = 1.0f / (1.0f + expf(-s));
        unsigned int bits = threefry_bits((unsigned int)(flat0 + e));
        float u = __uint_as_float((bits >> 9) | 0x3f800000u) - 1.0f;
        vs[e] = (u < p) ? 1.0f : 0.0f;
        float ax = fabsf(s);
        float lse = log1pf(expf(-ax));
        float spp = fmaxf(s, 0.0f) + lse;
        float spn = fmaxf(-s, 0.0f) + lse;
        ve[e] = p * spn + (1.0f - p) * spp;
    }
    ((float4*)out)[gid]                = make_float4(vs[0], vs[1], vs[2], vs[3]);
    ((float4*)(out + NTOT))[gid]       = make_float4(s4[0], s4[1], s4[2], s4[3]);
    ((float4*)(out + 2u * NTOT))[gid]  = make_float4(ve[0], ve[1], ve[2], ve[3]);
}

// ---------------- launch ----------------
extern "C" void kernel_launch(void* const* d_in, const int* in_sizes, int n_in,
                              void* d_out, int out_size) {
    const float* enc  = (const float*)d_in[0];
    const float* W    = (const float*)d_in[1];
    const float* Wl   = (const float*)d_in[2];
    const float* Wr   = (const float*)d_in[3];
    const float* U    = (const float*)d_in[4];
    const float* Bv   = (const float*)d_in[5];
    const float* lbias= (const float*)d_in[6];
    float* out = (float*)d_out;

    k_transpose<<<(Hh * Hh * Dd + 255) / 256, 256>>>(W, Wr);
    k_encT<<<dim3(4, 4, Bb), dim3(32, 8)>>>(enc);
    k_linear<<<(Bb * Ll * Dd + 255) / 256, 256>>>(enc, Wl, Bv);

    int smemG_bytes = 32768 + 65536 + 1024;    // 96 KB + prefetch pad
    cudaFuncSetAttribute(k_gemm1, cudaFuncAttributeMaxDynamicSharedMemorySize, smemG_bytes);
    k_gemm1<<<dim3(16, 2, Bb), 256, smemG_bytes>>>();

    int smemF_bytes = 65536 + 32768 + 4096 + 64;   // ~100 KB
    cudaFuncSetAttribute(k_final, cudaFuncAttributeMaxDynamicSharedMemorySize, smemF_bytes);
    k_final<<<dim3(2, 2, Bb), 256, smemF_bytes>>>(U);

    k_epi<<<NTOT / 4 / 256, 256>>>(lbias, out);
}

// round 8
// speedup vs baseline: 1.5495x; 1.0426x over previous
#include <cuda_runtime.h>
#include <math.h>

#define Bb 64
#define Ll 128
#define Hh 128
#define Dd 16
#define NTOT (Bb*Ll*Ll)        // 1048576

typedef unsigned long long u64;

// ---------------- scratch ----------------
__device__ float g_Wt[Hh*Dd*Hh];            // [k][d*128+n]   1 MB
__device__ float g_Wrt[Dd*Hh];              // [d*128+n]
__device__ float g_encT[Bb*Hh*Ll];          // [b][k][j]      4 MB
__device__ float g_Q[(size_t)Bb*Dd*Hh*Ll];  // [b][d][n][j]   64 MB
__device__ float g_c[Bb*Ll*Dd];             // [b][j][d]
__device__ float g_LP[2u*NTOT];             // [dh][b][j][m]  8 MB

// ---------------- packed f32x2 helpers ----------------
__device__ __forceinline__ u64 ffma2(u64 a, u64 b, u64 c) {
    u64 d; asm("fma.rn.f32x2 %0, %1, %2, %3;" : "=l"(d) : "l"(a), "l"(b), "l"(c));
    return d;
}
__device__ __forceinline__ u64 dup2(float v) {
    u64 d; asm("mov.b64 %0, {%1, %2};" : "=l"(d) : "f"(v), "f"(v));
    return d;
}
__device__ __forceinline__ float2 unpack2(u64 v) {
    float2 r; asm("mov.b64 {%0, %1}, %2;" : "=f"(r.x), "=f"(r.y) : "l"(v));
    return r;
}

// ---------------- JAX threefry2x32, partitionable, key=(0,1) --------------
__device__ __forceinline__ unsigned int rotl32(unsigned int v, int s) {
    return (v << s) | (v >> (32 - s));
}
__device__ __forceinline__ unsigned int threefry_bits(unsigned int i) {
    const unsigned int ks0 = 0u, ks1 = 1u, ks2 = 0x1BD11BDAu ^ 0u ^ 1u;
    unsigned int x0 = 0u + ks0;
    unsigned int x1 = i + ks1;
#define TFR(r) { x0 += x1; x1 = rotl32(x1, r) ^ x0; }
    TFR(13) TFR(15) TFR(26) TFR(6)   x0 += ks1; x1 += ks2 + 1u;
    TFR(17) TFR(29) TFR(16) TFR(24)  x0 += ks2; x1 += ks0 + 2u;
    TFR(13) TFR(15) TFR(26) TFR(6)   x0 += ks0; x1 += ks1 + 3u;
    TFR(17) TFR(29) TFR(16) TFR(24)  x0 += ks1; x1 += ks2 + 4u;
    TFR(13) TFR(15) TFR(26) TFR(6)   x0 += ks2; x1 += ks0 + 5u;
#undef TFR
    return x0 ^ x1;
}

__device__ __forceinline__ float tanh_fast(float x) {
    float e = __expf(2.0f * x);
    return 1.0f - __fdividef(2.0f, e + 1.0f);
}

// ---------------- kernel T: W[k,n,d] -> Wt[k][d*128+n]; Wr -> Wrt ---------
__global__ void k_transpose(const float* __restrict__ W, const float* __restrict__ Wr) {
    int idx = blockIdx.x * blockDim.x + threadIdx.x;
    if (idx < Hh * Hh * Dd) {
        int k = idx >> 11;
        int rem = idx & 2047;
        int d = rem >> 7;
        int n = rem & 127;
        g_Wt[idx] = W[(k * Hh + n) * Dd + d];
    }
    if (idx < Dd * Hh) {
        int d = idx >> 7, n = idx & 127;
        g_Wrt[idx] = Wr[n * Dd + d];
    }
}

// ---------------- kernel ET: enc[b][j][k] -> encT[b][k][j] ----------------
__global__ void k_encT(const float* __restrict__ enc) {
    __shared__ float t[32][33];
    int b = blockIdx.z;
    int j0 = blockIdx.x * 32, k0 = blockIdx.y * 32;
    int tx = threadIdx.x, ty = threadIdx.y;   // block (32, 8)
#pragma unroll
    for (int i = 0; i < 32; i += 8)
        t[ty + i][tx] = enc[b * 16384 + (j0 + ty + i) * 128 + k0 + tx];
    __syncthreads();
#pragma unroll
    for (int i = 0; i < 32; i += 8)
        g_encT[b * 16384 + (k0 + ty + i) * 128 + j0 + tx] = t[tx][ty + i];
}

// ---------------- kernel C: c[b,j,d] = enc[b,j,:].Wl[:,d] + Bvec[d] -------
__global__ void k_linear(const float* __restrict__ enc, const float* __restrict__ Wl,
                         const float* __restrict__ Bvec) {
    int idx = blockIdx.x * blockDim.x + threadIdx.x;
    if (idx >= Bb * Ll * Dd) return;
    int d = idx & 15;
    int bj = idx >> 4;
    const float* e = enc + (size_t)bj * Hh;
    float acc = Bvec[d];
#pragma unroll 8
    for (int k = 0; k < Hh; k++) acc = fmaf(e[k], Wl[k * Dd + d], acc);
    g_c[idx] = acc;
}

// 8 rows x 8 cols (4 u64 col-pairs): cols tx*4..+3 and 64+tx*4..+3
#define ROWOP8(r, aval) { u64 a_ = dup2(aval); \
    acc[r][0] = ffma2(a_, b01.x, acc[r][0]); \
    acc[r][1] = ffma2(a_, b01.y, acc[r][1]); \
    acc[r][2] = ffma2(a_, b23.x, acc[r][2]); \
    acc[r][3] = ffma2(a_, b23.y, acc[r][3]); }

// 8 rows x 4 cols (2 u64 col-pairs): cols tx*4..+3
#define ROWOP2(r, aval) { u64 a_ = dup2(aval); \
    acc[r][0] = ffma2(a_, b01.x, acc[r][0]); \
    acc[r][1] = ffma2(a_, b01.y, acc[r][1]); }

// ---------------- kernel 1: Q[b][d][n][j] = (enc_b @ Wt_d)^T + Wrt --------
// grid (16 d, 64 b), block 256, tile 128j x 128n, per-thread 8x8, k-chunks of 64
extern __shared__ char smemG[];
__global__ __launch_bounds__(256, 2) void k_gemm1() {
    float* sB = (float*)smemG;                 // Wt_d [128 k][128 n] 64 KB
    float* sA = (float*)(smemG + 65536);       // encT chunk [64 k][128 j] 32 KB (+pad)
    int d = blockIdx.x, b = blockIdx.y;
    int tid = threadIdx.x;
    int tx = tid & 15, ty = tid >> 4;          // cols tx*4 & 64+tx*4, rows ty*8

    // stage sB: Wt[k][d*128 + n], all 128 k
    {
        const float4* src = (const float4*)g_Wt;
        float4* dst = (float4*)sB;
        for (int idx = tid; idx < 4096; idx += 256) {
            int k = idx >> 5, g = idx & 31;
            dst[k * 32 + g] = src[k * 512 + d * 32 + g];
        }
    }

    u64 acc[8][4];
#pragma unroll
    for (int r = 0; r < 8; r++)
#pragma unroll
        for (int q = 0; q < 4; q++) acc[r][q] = 0ull;

    for (int kc = 0; kc < 2; kc++) {
        __syncthreads();   // sB ready / prev chunk compute done
        // stage sA chunk: encT rows kc*64..+63, all 128 j
        {
            const float4* src = (const float4*)(g_encT + (size_t)b * 16384);
            float4* dst = (float4*)sA;
            for (int idx = tid; idx < 2048; idx += 256) {
                int kk = idx >> 5, g = idx & 31;
                dst[kk * 32 + g] = src[(kc * 64 + kk) * 32 + g];
            }
        }
        __syncthreads();

        int k0 = kc * 64;
        float4 a01_nx = *(const float4*)&sA[ty * 8];
        float4 a23_nx = *(const float4*)&sA[ty * 8 + 4];
        ulonglong2 b01_nx = *(const ulonglong2*)&sB[k0 * 128 + tx * 4];
        ulonglong2 b23_nx = *(const ulonglong2*)&sB[k0 * 128 + 64 + tx * 4];
#pragma unroll 4
        for (int kk = 0; kk < 64; kk++) {
            float4 a01 = a01_nx, a23 = a23_nx;
            ulonglong2 b01 = b01_nx, b23 = b23_nx;
            int kn = kk + 1;   // kk=63: stray reads into pad / adjacent region
            a01_nx = *(const float4*)&sA[kn * 128 + ty * 8];
            a23_nx = *(const float4*)&sA[kn * 128 + ty * 8 + 4];
            b01_nx = *(const ulonglong2*)&sB[(k0 + kn) * 128 + tx * 4];
            b23_nx = *(const ulonglong2*)&sB[(k0 + kn) * 128 + 64 + tx * 4];
            ROWOP8(0, a01.x) ROWOP8(1, a01.y) ROWOP8(2, a01.z) ROWOP8(3, a01.w)
            ROWOP8(4, a23.x) ROWOP8(5, a23.y) ROWOP8(6, a23.z) ROWOP8(7, a23.w)
        }
    }

    // epilogue: unpack, add Wrt, store transposed [n][j]
#pragma unroll
    for (int q = 0; q < 4; q++) {
        int colbase = (q < 2) ? (tx * 4 + 2 * q) : (64 + tx * 4 + 2 * (q - 2));
#pragma unroll
        for (int h = 0; h < 2; h++) {
            int col = colbase + h;
            float wr = g_Wrt[d * 128 + col];
            float v[8];
#pragma unroll
            for (int r = 0; r < 8; r++) {
                float2 s = unpack2(acc[r][q]);
                v[r] = (h == 0 ? s.x : s.y) + wr;
            }
            float* dst = g_Q + ((size_t)(b * 16 + d) * 128 + col) * 128 + ty * 8;
            *(float4*)dst       = make_float4(v[0], v[1], v[2], v[3]);
            *(float4*)(dst + 4) = make_float4(v[4], v[5], v[6], v[7]);
        }
    }
}

// ---------------- kernel 2: bilinear + tanh + partial logits --------------
// grid (2 mh, 2 dh, 64 b), block 256, tile 128j x 64m, per-thread 8x4, 8 d's
extern __shared__ char smemF[];
__global__ __launch_bounds__(256, 2) void k_final(const float* __restrict__ U) {
    float* sQ = (float*)smemF;                 // Q_d [128 n][128 j] 64 KB
    float* sE = (float*)(smemF + 65536);       // encT m-half [128 n][64 m] 32 KB
    float* sC = (float*)(smemF + 65536 + 32768);   // c[b] [128 j][16 d] 8 KB
    float* sU = sC + 2048;
    int mh = blockIdx.x, dh = blockIdx.y, b = blockIdx.z;
    int tid = threadIdx.x;
    int tx = tid & 15, ty = tid >> 4;          // m cols mh*64+tx*4, j rows ty*8

    // stage sE (m-half of encT for b), sC, sU
    {
        const float4* src = (const float4*)(g_encT + (size_t)b * 16384);
        float4* dst = (float4*)sE;
        for (int idx = tid; idx < 2048; idx += 256) {
            int n = idx >> 4, g = idx & 15;
            dst[n * 16 + g] = src[n * 32 + mh * 16 + g];
        }
        const float4* csrc = (const float4*)(g_c + b * 2048);
        float4* cdst = (float4*)sC;
        for (int idx = tid; idx < 512; idx += 256) cdst[idx] = csrc[idx];
        if (tid < 16) sU[tid] = U[tid];
    }

    float logit[8][4];
#pragma unroll
    for (int r = 0; r < 8; r++)
#pragma unroll
        for (int q = 0; q < 4; q++) logit[r][q] = 0.0f;

    for (int dd = 0; dd < 8; dd++) {
        int d = dh * 8 + dd;
        __syncthreads();
        // stage sQ: Q[b][d] (contiguous 64 KB)
        {
            const float4* src = (const float4*)(g_Q + (size_t)(b * 16 + d) * 16384);
            float4* dst = (float4*)sQ;
            for (int idx = tid; idx < 4096; idx += 256) dst[idx] = src[idx];
        }
        __syncthreads();

        u64 acc[8][2];
#pragma unroll
        for (int r = 0; r < 8; r++) { acc[r][0] = 0ull; acc[r][1] = 0ull; }

        float4 a01_nx = *(const float4*)&sQ[ty * 8];
        float4 a23_nx = *(const float4*)&sQ[ty * 8 + 4];
        ulonglong2 b01_nx = *(const ulonglong2*)&sE[tx * 4];
#pragma unroll 4
        for (int n = 0; n < 128; n++) {
            float4 a01 = a01_nx, a23 = a23_nx;
            ulonglong2 b01 = b01_nx;
            int nn = n + 1;   // n=127: stray reads land in following regions
            a01_nx = *(const float4*)&sQ[nn * 128 + ty * 8];
            a23_nx = *(const float4*)&sQ[nn * 128 + ty * 8 + 4];
            b01_nx = *(const ulonglong2*)&sE[nn * 64 + tx * 4];
            ROWOP2(0, a01.x) ROWOP2(1, a01.y) ROWOP2(2, a01.z) ROWOP2(3, a01.w)
            ROWOP2(4, a23.x) ROWOP2(5, a23.y) ROWOP2(6, a23.z) ROWOP2(7, a23.w)
        }

        float ud = sU[d];
#pragma unroll
        for (int r = 0; r < 8; r++) {
            float cr = sC[(ty * 8 + r) * 16 + d];
            float2 s0 = unpack2(acc[r][0]);
            float2 s1 = unpack2(acc[r][1]);
            logit[r][0] = fmaf(ud, tanh_fast(s0.x + cr), logit[r][0]);
            logit[r][1] = fmaf(ud, tanh_fast(s0.y + cr), logit[r][1]);
            logit[r][2] = fmaf(ud, tanh_fast(s1.x + cr), logit[r][2]);
            logit[r][3] = fmaf(ud, tanh_fast(s1.y + cr), logit[r][3]);
        }
    }

    // write partial logits: g_LP[dh*NTOT + b*16384 + j*128 + mh*64 + tx*4]
#pragma unroll
    for (int r = 0; r < 8; r++) {
        int j = ty * 8 + r;
        size_t o = (size_t)dh * NTOT + (size_t)b * 16384 + (size_t)j * 128 + mh * 64 + tx * 4;
        *(float4*)(g_LP + o) = make_float4(logit[r][0], logit[r][1], logit[r][2], logit[r][3]);
    }
}

// ---------------- kernel E: combine + mask/sigmoid/RNG/entropy ------------
__global__ __launch_bounds__(256) void k_epi(const float* __restrict__ lb,
                                             float* __restrict__ out) {
    int gid = blockIdx.x * blockDim.x + threadIdx.x;   // < NTOT/4
    const float4* P0 = (const float4*)g_LP;
    const float4* P1 = P0 + (NTOT / 4);
    float4 a = P0[gid], c = P1[gid];
    float lbias = lb[0];
    float s4[4] = { a.x + c.x + lbias, a.y + c.y + lbias,
                    a.z + c.z + lbias, a.w + c.w + lbias };
    int flat0 = gid * 4;
    int j = (flat0 >> 7) & 127;
    int m0 = flat0 & 127;
    float vs[4], ve[4];
#pragma unroll
    for (int e = 0; e < 4; e++) {
        float s = s4[e];
        if (j == m0 + e) s -= 1e8f;
        s4[e] = s;
        float p = 1.0f / (1.0f + expf(-s));
        unsigned int bits = threefry_bits((unsigned int)(flat0 + e));
        float u = __uint_as_float((bits >> 9) | 0x3f800000u) - 1.0f;
        vs[e] = (u < p) ? 1.0f : 0.0f;
        float ax = fabsf(s);
        float lse = log1pf(expf(-ax));
        float spp = fmaxf(s, 0.0f) + lse;
        float spn = fmaxf(-s, 0.0f) + lse;
        ve[e] = p * spn + (1.0f - p) * spp;
    }
    ((float4*)out)[gid]                = make_float4(vs[0], vs[1], vs[2], vs[3]);
    ((float4*)(out + NTOT))[gid]       = make_float4(s4[0], s4[1], s4[2], s4[3]);
    ((float4*)(out + 2u * NTOT))[gid]  = make_float4(ve[0], ve[1], ve[2], ve[3]);
}

// ---------------- launch ----------------
extern "C" void kernel_launch(void* const* d_in, const int* in_sizes, int n_in,
                              void* d_out, int out_size) {
    const float* enc  = (const float*)d_in[0];
    const float* W    = (const float*)d_in[1];
    const float* Wl   = (const float*)d_in[2];
    const float* Wr   = (const float*)d_in[3];
    const float* U    = (const float*)d_in[4];
    const float* Bv   = (const float*)d_in[5];
    const float* lbias= (const float*)d_in[6];
    float* out = (float*)d_out;

    k_transpose<<<(Hh * Hh * Dd + 255) / 256, 256>>>(W, Wr);
    k_encT<<<dim3(4, 4, Bb), dim3(32, 8)>>>(enc);
    k_linear<<<(Bb * Ll * Dd + 255) / 256, 256>>>(enc, Wl, Bv);

    int smemG_bytes = 65536 + 32768 + 1024;    // sB + sA chunk + prefetch pad
    cudaFuncSetAttribute(k_gemm1, cudaFuncAttributeMaxDynamicSharedMemorySize, smemG_bytes);
    k_gemm1<<<dim3(16, Bb), 256, smemG_bytes>>>();

    int smemF_bytes = 65536 + 32768 + 8192 + 64 + 512;   // sQ + sE + sC + sU + pad
    cudaFuncSetAttribute(k_final, cudaFuncAttributeMaxDynamicSharedMemorySize, smemF_bytes);
    k_final<<<dim3(2, 2, Bb), 256, smemF_bytes>>>(U);

    k_epi<<<NTOT / 4 / 256, 256>>>(lbias, out);
}

// round 9
// speedup vs baseline: 1.7501x; 1.1295x over previous
#include <cuda_runtime.h>
#include <math.h>

#define Bb 64
#define Ll 128
#define Hh 128
#define Dd 16
#define NTOT (Bb*Ll*Ll)        // 1048576

typedef unsigned long long u64;

// ---------------- scratch ----------------
__device__ float g_Wt[Hh*Dd*Hh];            // [k][d*128+n]   1 MB
__device__ float g_Wrt[Dd*Hh];              // [d*128+n]
__device__ float g_encT[Bb*Hh*Ll];          // [b][k][j]      4 MB
__device__ float g_Q[(size_t)Bb*Dd*Hh*Ll];  // [b][d][n][j]   64 MB
__device__ float g_c[Bb*Ll*Dd];             // [b][j][d]
__device__ float g_LP[2u*NTOT];             // [dh][b][j][m]  8 MB

// ---------------- packed f32x2 helpers ----------------
__device__ __forceinline__ u64 ffma2(u64 a, u64 b, u64 c) {
    u64 d; asm("fma.rn.f32x2 %0, %1, %2, %3;" : "=l"(d) : "l"(a), "l"(b), "l"(c));
    return d;
}
__device__ __forceinline__ u64 dup2(float v) {
    u64 d; asm("mov.b64 %0, {%1, %2};" : "=l"(d) : "f"(v), "f"(v));
    return d;
}
__device__ __forceinline__ float2 unpack2(u64 v) {
    float2 r; asm("mov.b64 {%0, %1}, %2;" : "=f"(r.x), "=f"(r.y) : "l"(v));
    return r;
}

// ---------------- cp.async helpers ----------------
__device__ __forceinline__ unsigned int s2u(const void* p) {
    return (unsigned int)__cvta_generic_to_shared(p);
}
__device__ __forceinline__ void cpa16(unsigned int s, const void* g) {
    asm volatile("cp.async.cg.shared.global [%0], [%1], 16;" :: "r"(s), "l"(g));
}
__device__ __forceinline__ void cpa_commit() {
    asm volatile("cp.async.commit_group;" ::: "memory");
}
template<int N> __device__ __forceinline__ void cpa_wait() {
    asm volatile("cp.async.wait_group %0;" :: "n"(N) : "memory");
}

// ---------------- JAX threefry2x32, partitionable, key=(0,1) --------------
__device__ __forceinline__ unsigned int rotl32(unsigned int v, int s) {
    return (v << s) | (v >> (32 - s));
}
__device__ __forceinline__ unsigned int threefry_bits(unsigned int i) {
    const unsigned int ks0 = 0u, ks1 = 1u, ks2 = 0x1BD11BDAu ^ 0u ^ 1u;
    unsigned int x0 = 0u + ks0;
    unsigned int x1 = i + ks1;
#define TFR(r) { x0 += x1; x1 = rotl32(x1, r) ^ x0; }
    TFR(13) TFR(15) TFR(26) TFR(6)   x0 += ks1; x1 += ks2 + 1u;
    TFR(17) TFR(29) TFR(16) TFR(24)  x0 += ks2; x1 += ks0 + 2u;
    TFR(13) TFR(15) TFR(26) TFR(6)   x0 += ks0; x1 += ks1 + 3u;
    TFR(17) TFR(29) TFR(16) TFR(24)  x0 += ks1; x1 += ks2 + 4u;
    TFR(13) TFR(15) TFR(26) TFR(6)   x0 += ks2; x1 += ks0 + 5u;
#undef TFR
    return x0 ^ x1;
}

__device__ __forceinline__ float tanh_fast(float x) {
    float e = __expf(2.0f * x);
    return 1.0f - __fdividef(2.0f, e + 1.0f);
}

// ---------------- kernel T ----------------
__global__ void k_transpose(const float* __restrict__ W, const float* __restrict__ Wr) {
    int idx = blockIdx.x * blockDim.x + threadIdx.x;
    if (idx < Hh * Hh * Dd) {
        int k = idx >> 11;
        int rem = idx & 2047;
        int d = rem >> 7;
        int n = rem & 127;
        g_Wt[idx] = W[(k * Hh + n) * Dd + d];
    }
    if (idx < Dd * Hh) {
        int d = idx >> 7, n = idx & 127;
        g_Wrt[idx] = Wr[n * Dd + d];
    }
}

// ---------------- kernel ET ----------------
__global__ void k_encT(const float* __restrict__ enc) {
    __shared__ float t[32][33];
    int b = blockIdx.z;
    int j0 = blockIdx.x * 32, k0 = blockIdx.y * 32;
    int tx = threadIdx.x, ty = threadIdx.y;
#pragma unroll
    for (int i = 0; i < 32; i += 8)
        t[ty + i][tx] = enc[b * 16384 + (j0 + ty + i) * 128 + k0 + tx];
    __syncthreads();
#pragma unroll
    for (int i = 0; i < 32; i += 8)
        g_encT[b * 16384 + (k0 + ty + i) * 128 + j0 + tx] = t[tx][ty + i];
}

// ---------------- kernel C ----------------
__global__ void k_linear(const float* __restrict__ enc, const float* __restrict__ Wl,
                         const float* __restrict__ Bvec) {
    int idx = blockIdx.x * blockDim.x + threadIdx.x;
    if (idx >= Bb * Ll * Dd) return;
    int d = idx & 15;
    int bj = idx >> 4;
    const float* e = enc + (size_t)bj * Hh;
    float acc = Bvec[d];
#pragma unroll 8
    for (int k = 0; k < Hh; k++) acc = fmaf(e[k], Wl[k * Dd + d], acc);
    g_c[idx] = acc;
}

#define ROWOP8(r, aval) { u64 a_ = dup2(aval); \
    acc[r][0] = ffma2(a_, b01.x, acc[r][0]); \
    acc[r][1] = ffma2(a_, b01.y, acc[r][1]); \
    acc[r][2] = ffma2(a_, b23.x, acc[r][2]); \
    acc[r][3] = ffma2(a_, b23.y, acc[r][3]); }

#define ROWOP2(r, aval) { u64 a_ = dup2(aval); \
    acc[r][0] = ffma2(a_, b01.x, acc[r][0]); \
    acc[r][1] = ffma2(a_, b01.y, acc[r][1]); }

// ---------------- kernel 1: Q[b][d][n][j] = (enc_b @ Wt_d)^T + Wrt --------
// grid (16 d, 64 b), block 256, tile 128j x 128n, 8x8/thread,
// cp.async double-buffered sA chunks of 32 k
extern __shared__ char smemG[];
__global__ __launch_bounds__(256, 2) void k_gemm1() {
    float* sB  = (float*)smemG;                    // [128 k][128 n] 64 KB
    float* sA0 = (float*)(smemG + 65536);          // chunk buf 0: [32 k][128 j] 16 KB
    float* sA1 = (float*)(smemG + 65536 + 16384);  // chunk buf 1
    int d = blockIdx.x, b = blockIdx.y;
    int tid = threadIdx.x;
    int tx = tid & 15, ty = tid >> 4;

    const float4* wsrc = (const float4*)g_Wt;
    const float4* asrc = (const float4*)(g_encT + (size_t)b * 16384);

    // prologue: async stage sB + chunk0 (group0), chunk1 (group1)
    {
        unsigned int sBa = s2u(sB);
        for (int idx = tid; idx < 4096; idx += 256) {
            int k = idx >> 5, g = idx & 31;
            cpa16(sBa + (unsigned)(k * 32 + g) * 16, wsrc + (size_t)k * 512 + d * 32 + g);
        }
        unsigned int a0 = s2u(sA0);
        for (int idx = tid; idx < 1024; idx += 256)
            cpa16(a0 + (unsigned)idx * 16, asrc + idx);
        cpa_commit();
        unsigned int a1 = s2u(sA1);
        for (int idx = tid; idx < 1024; idx += 256)
            cpa16(a1 + (unsigned)idx * 16, asrc + 1024 + idx);
        cpa_commit();
    }
    cpa_wait<1>();
    __syncthreads();

    u64 acc[8][4];
#pragma unroll
    for (int r = 0; r < 8; r++)
#pragma unroll
        for (int q = 0; q < 4; q++) acc[r][q] = 0ull;

    for (int kc = 0; kc < 4; kc++) {
        float* sAc = (kc & 1) ? sA1 : sA0;
        int k0 = kc * 32;
        float4 a01_nx = *(const float4*)&sAc[ty * 8];
        float4 a23_nx = *(const float4*)&sAc[ty * 8 + 4];
        ulonglong2 b01_nx = *(const ulonglong2*)&sB[k0 * 128 + tx * 4];
        ulonglong2 b23_nx = *(const ulonglong2*)&sB[k0 * 128 + 64 + tx * 4];
#pragma unroll 4
        for (int kk = 0; kk < 32; kk++) {
            float4 a01 = a01_nx, a23 = a23_nx;
            ulonglong2 b01 = b01_nx, b23 = b23_nx;
            int kn = kk + 1;   // kk=31: stray reads into next buffer / pad (unused)
            a01_nx = *(const float4*)&sAc[kn * 128 + ty * 8];
            a23_nx = *(const float4*)&sAc[kn * 128 + ty * 8 + 4];
            b01_nx = *(const ulonglong2*)&sB[(k0 + kn) * 128 + tx * 4];
            b23_nx = *(const ulonglong2*)&sB[(k0 + kn) * 128 + 64 + tx * 4];
            ROWOP8(0, a01.x) ROWOP8(1, a01.y) ROWOP8(2, a01.z) ROWOP8(3, a01.w)
            ROWOP8(4, a23.x) ROWOP8(5, a23.y) ROWOP8(6, a23.z) ROWOP8(7, a23.w)
        }
        __syncthreads();   // all warps done reading sAc
        if (kc + 2 < 4) {
            unsigned int aa = s2u(sAc);
            for (int idx = tid; idx < 1024; idx += 256)
                cpa16(aa + (unsigned)idx * 16, asrc + (kc + 2) * 1024 + idx);
            cpa_commit();
            cpa_wait<1>();
        } else {
            cpa_wait<0>();
        }
        __syncthreads();
    }

    // epilogue: unpack, add Wrt, store transposed [n][j]
#pragma unroll
    for (int q = 0; q < 4; q++) {
        int colbase = (q < 2) ? (tx * 4 + 2 * q) : (64 + tx * 4 + 2 * (q - 2));
#pragma unroll
        for (int h = 0; h < 2; h++) {
            int col = colbase + h;
            float wr = g_Wrt[d * 128 + col];
            float v[8];
#pragma unroll
            for (int r = 0; r < 8; r++) {
                float2 s = unpack2(acc[r][q]);
                v[r] = (h == 0 ? s.x : s.y) + wr;
            }
            float* dst = g_Q + ((size_t)(b * 16 + d) * 128 + col) * 128 + ty * 8;
            *(float4*)dst       = make_float4(v[0], v[1], v[2], v[3]);
            *(float4*)(dst + 4) = make_float4(v[4], v[5], v[6], v[7]);
        }
    }
}

// ---------------- kernel 2: bilinear + tanh + partial logits --------------
// grid (2 mh, 2 dh, 64 b), block 256, tile 128j x 64m, 8x4/thread,
// cp.async ring-buffered sQ in n-halves (16 phases)
extern __shared__ char smemF[];
__global__ __launch_bounds__(256, 2) void k_final(const float* __restrict__ U) {
    float* sQ0 = (float*)smemF;                    // [64 n][128 j] 32 KB
    float* sQ1 = (float*)(smemF + 32768);          // [64 n][128 j] 32 KB
    float* sE  = (float*)(smemF + 65536);          // [128 n][64 m] 32 KB
    float* sC  = (float*)(smemF + 98304);          // [128 j][16 d] 8 KB
    float* sU  = sC + 2048;
    int mh = blockIdx.x, dh = blockIdx.y, b = blockIdx.z;
    int tid = threadIdx.x;
    int tx = tid & 15, ty = tid >> 4;

    const float4* qsrc = (const float4*)g_Q;   // [b*16+d][4096 float4]

    // prologue: async sE + phase0 (group0), phase1 (group1); sync loads for sC/sU
    {
        const float4* esrc = (const float4*)(g_encT + (size_t)b * 16384);
        unsigned int ea = s2u(sE);
        for (int idx = tid; idx < 2048; idx += 256) {
            int n = idx >> 4, g = idx & 15;
            cpa16(ea + (unsigned)idx * 16, esrc + n * 32 + mh * 16 + g);
        }
        int d0 = dh * 8;
        unsigned int q0 = s2u(sQ0);
        for (int idx = tid; idx < 2048; idx += 256)
            cpa16(q0 + (unsigned)idx * 16, qsrc + (size_t)(b * 16 + d0) * 4096 + idx);
        cpa_commit();
        unsigned int q1 = s2u(sQ1);
        for (int idx = tid; idx < 2048; idx += 256)
            cpa16(q1 + (unsigned)idx * 16, qsrc + (size_t)(b * 16 + d0) * 4096 + 2048 + idx);
        cpa_commit();
        const float4* csrc = (const float4*)(g_c + b * 2048);
        float4* cdst = (float4*)sC;
        for (int idx = tid; idx < 512; idx += 256) cdst[idx] = csrc[idx];
        if (tid < 16) sU[tid] = U[tid];
    }
    cpa_wait<1>();
    __syncthreads();

    float logit[8][4];
#pragma unroll
    for (int r = 0; r < 8; r++)
#pragma unroll
        for (int q = 0; q < 4; q++) logit[r][q] = 0.0f;

    u64 acc[8][2];

    for (int p = 0; p < 16; p++) {
        int dloc = p >> 1, hh = p & 1;
        int d = dh * 8 + dloc;
        float* sQc = hh ? sQ1 : sQ0;
        if (hh == 0) {
#pragma unroll
            for (int r = 0; r < 8; r++) { acc[r][0] = 0ull; acc[r][1] = 0ull; }
        }
        {
            float4 a01_nx = *(const float4*)&sQc[ty * 8];
            float4 a23_nx = *(const float4*)&sQc[ty * 8 + 4];
            ulonglong2 b01_nx = *(const ulonglong2*)&sE[(hh * 64) * 64 + tx * 4];
#pragma unroll 4
            for (int nn = 0; nn < 64; nn++) {
                float4 a01 = a01_nx, a23 = a23_nx;
                ulonglong2 b01 = b01_nx;
                int kn = nn + 1;   // nn=63: stray reads into next region (unused)
                a01_nx = *(const float4*)&sQc[kn * 128 + ty * 8];
                a23_nx = *(const float4*)&sQc[kn * 128 + ty * 8 + 4];
                b01_nx = *(const ulonglong2*)&sE[(hh * 64 + kn) * 64 + tx * 4];
                ROWOP2(0, a01.x) ROWOP2(1, a01.y) ROWOP2(2, a01.z) ROWOP2(3, a01.w)
                ROWOP2(4, a23.x) ROWOP2(5, a23.y) ROWOP2(6, a23.z) ROWOP2(7, a23.w)
            }
        }
        if (hh == 1) {
            float ud = sU[d];
#pragma unroll
            for (int r = 0; r < 8; r++) {
                float cr = sC[(ty * 8 + r) * 16 + d];
                float2 s0 = unpack2(acc[r][0]);
                float2 s1 = unpack2(acc[r][1]);
                logit[r][0] = fmaf(ud, tanh_fast(s0.x + cr), logit[r][0]);
                logit[r][1] = fmaf(ud, tanh_fast(s0.y + cr), logit[r][1]);
                logit[r][2] = fmaf(ud, tanh_fast(s1.x + cr), logit[r][2]);
                logit[r][3] = fmaf(ud, tanh_fast(s1.y + cr), logit[r][3]);
            }
        }
        __syncthreads();   // all warps done reading sQc
        if (p + 2 < 16) {
            int p2 = p + 2;
            int d2 = dh * 8 + (p2 >> 1), h2 = p2 & 1;
            unsigned int qa = s2u(sQc);
            for (int idx = tid; idx < 2048; idx += 256)
                cpa16(qa + (unsigned)idx * 16,
                      qsrc + (size_t)(b * 16 + d2) * 4096 + h2 * 2048 + idx);
            cpa_commit();
            cpa_wait<1>();
        } else {
            cpa_wait<0>();
        }
        __syncthreads();
    }

    // write partial logits
#pragma unroll
    for (int r = 0; r < 8; r++) {
        int j = ty * 8 + r;
        size_t o = (size_t)dh * NTOT + (size_t)b * 16384 + (size_t)j * 128 + mh * 64 + tx * 4;
        *(float4*)(g_LP + o) = make_float4(logit[r][0], logit[r][1], logit[r][2], logit[r][3]);
    }
}

// ---------------- kernel E: combine + mask/sigmoid/RNG/entropy ------------
__global__ __launch_bounds__(256) void k_epi(const float* __restrict__ lb,
                                             float* __restrict__ out) {
    int gid = blockIdx.x * blockDim.x + threadIdx.x;
    const float4* P0 = (const float4*)g_LP;
    const float4* P1 = P0 + (NTOT / 4);
    float4 a = P0[gid], c = P1[gid];
    float lbias = lb[0];
    float s4[4] = { a.x + c.x + lbias, a.y + c.y + lbias,
                    a.z + c.z + lbias, a.w + c.w + lbias };
    int flat0 = gid * 4;
    int j = (flat0 >> 7) & 127;
    int m0 = flat0 & 127;
    float vs[4], ve[4];
#pragma unroll
    for (int e = 0; e < 4; e++) {
        float s = s4[e];
        if (j == m0 + e) s -= 1e8f;
        s4[e] = s;
        float p = 1.0f / (1.0f + expf(-s));
        unsigned int bits = threefry_bits((unsigned int)(flat0 + e));
        float u = __uint_as_float((bits >> 9) | 0x3f800000u) - 1.0f;
        vs[e] = (u < p) ? 1.0f : 0.0f;
        float ax = fabsf(s);
        float lse = log1pf(expf(-ax));
        float spp = fmaxf(s, 0.0f) + lse;
        float spn = fmaxf(-s, 0.0f) + lse;
        ve[e] = p * spn + (1.0f - p) * spp;
    }
    ((float4*)out)[gid]                = make_float4(vs[0], vs[1], vs[2], vs[3]);
    ((float4*)(out + NTOT))[gid]       = make_float4(s4[0], s4[1], s4[2], s4[3]);
    ((float4*)(out + 2u * NTOT))[gid]  = make_float4(ve[0], ve[1], ve[2], ve[3]);
}

// ---------------- launch ----------------
extern "C" void kernel_launch(void* const* d_in, const int* in_sizes, int n_in,
                              void* d_out, int out_size) {
    const float* enc  = (const float*)d_in[0];
    const float* W    = (const float*)d_in[1];
    const float* Wl   = (const float*)d_in[2];
    const float* Wr   = (const float*)d_in[3];
    const float* U    = (const float*)d_in[4];
    const float* Bv   = (const float*)d_in[5];
    const float* lbias= (const float*)d_in[6];
    float* out = (float*)d_out;

    k_transpose<<<(Hh * Hh * Dd + 255) / 256, 256>>>(W, Wr);
    k_encT<<<dim3(4, 4, Bb), dim3(32, 8)>>>(enc);
    k_linear<<<(Bb * Ll * Dd + 255) / 256, 256>>>(enc, Wl, Bv);

    int smemG_bytes = 65536 + 32768 + 1024;    // sB + 2 sA bufs + prefetch pad
    cudaFuncSetAttribute(k_gemm1, cudaFuncAttributeMaxDynamicSharedMemorySize, smemG_bytes);
    k_gemm1<<<dim3(16, Bb), 256, smemG_bytes>>>();

    int smemF_bytes = 32768 * 2 + 32768 + 8192 + 64 + 512;  // 2 sQ bufs + sE + sC + sU + pad
    cudaFuncSetAttribute(k_final, cudaFuncAttributeMaxDynamicSharedMemorySize, smemF_bytes);
    k_final<<<dim3(2, 2, Bb), 256, smemF_bytes>>>(U);

    k_epi<<<NTOT / 4 / 256, 256>>>(lbias, out);
}